// round 10
// baseline (speedup 1.0000x reference)
#include <cuda_runtime.h>
#include <cuda_bf16.h>
#include <math.h>
#include <stdint.h>

// Problem constants
#define BB   256
#define TT   1024
#define DD   256
#define UU   128
#define GG   384      // 3*U
#define MM   (BB*TT)  // 262144 rows

// Scratch (device globals — no allocation allowed)
__device__ float g_xproj[(size_t)MM * GG];        // [B*T, 384]
__device__ float g_fg[(size_t)MM * UU];           // [B*T, 128]
__device__ __nv_bfloat16 g_ahi[(size_t)MM * DD];  // bf16 hi split of inputs
__device__ __nv_bfloat16 g_alo[(size_t)MM * DD];  // bf16 lo split
__device__ __nv_bfloat16 g_bhi[(size_t)GG * DD];  // W^T hi: [384,256]
__device__ __nv_bfloat16 g_blo[(size_t)GG * DD];  // W^T lo
__device__ __nv_bfloat16 g_rk[(size_t)GG * UU];   // rk^T bf16 hi: [384,128]
__device__ int g_flags[8 * 256];                  // [chunk][batch] -> 3 when ready

// ---------------------------------------------------------------------------
__device__ __forceinline__ uint32_t s2u(const void* p) {
    uint32_t a;
    asm("{ .reg .u64 t; cvta.to.shared.u64 t, %1; cvt.u32.u64 %0, t; }"
        : "=r"(a) : "l"(p));
    return a;
}

#define SW128(o) ((o) ^ (((o) >> 3) & 0x70))

__device__ __forceinline__ void ldsm_x4(uint32_t* r, uint32_t addr) {
    asm volatile("ldmatrix.sync.aligned.m8n8.x4.shared.b16 {%0,%1,%2,%3}, [%4];"
                 : "=r"(r[0]), "=r"(r[1]), "=r"(r[2]), "=r"(r[3]) : "r"(addr));
}

__device__ __forceinline__ void mma_bf16(float* d, const uint32_t* a,
                                         const uint32_t* b) {
    asm volatile(
        "mma.sync.aligned.m16n8k16.row.col.f32.bf16.bf16.f32 "
        "{%0,%1,%2,%3}, {%4,%5,%6,%7}, {%8,%9}, {%0,%1,%2,%3};"
        : "+f"(d[0]), "+f"(d[1]), "+f"(d[2]), "+f"(d[3])
        : "r"(a[0]), "r"(a[1]), "r"(a[2]), "r"(a[3]), "r"(b[0]), "r"(b[1]));
}

__device__ __forceinline__ void cp16(uint32_t dst, const void* src) {
    asm volatile("cp.async.cg.shared.global [%0], [%1], 16;"
                 :: "r"(dst), "l"(src) : "memory");
}
__device__ __forceinline__ void cp_commit() {
    asm volatile("cp.async.commit_group;" ::: "memory");
}
template <int N>
__device__ __forceinline__ void cp_wait() {
    asm volatile("cp.async.wait_group %0;" :: "n"(N) : "memory");
}

__device__ __forceinline__ float tanh_apx(float x) {
    float y;
    asm("tanh.approx.f32 %0, %1;" : "=f"(y) : "f"(x));
    return y;
}
__device__ __forceinline__ float fsig(float x) {
    return __fdividef(1.0f, 1.0f + __expf(-x));
}

// ---------------------------------------------------------------------------
// zero the readiness flags (must precede gemm + scan each call)
// ---------------------------------------------------------------------------
__global__ void zero_flags() {
    g_flags[blockIdx.x * 256 + threadIdx.x] = 0;
}

// ---------------------------------------------------------------------------
// Split conversions
// ---------------------------------------------------------------------------
__global__ __launch_bounds__(256) void convert_a(const float* __restrict__ in) {
    size_t i = ((size_t)blockIdx.x * 256 + threadIdx.x) * 4;
    float4 v = *(const float4*)(in + i);
    float vv[4] = {v.x, v.y, v.z, v.w};
    unsigned short hb[4], lb[4];
#pragma unroll
    for (int j = 0; j < 4; ++j) {
        __nv_bfloat16 h = __float2bfloat16(vv[j]);
        __nv_bfloat16 l = __float2bfloat16(vv[j] - __bfloat162float(h));
        hb[j] = *reinterpret_cast<unsigned short*>(&h);
        lb[j] = *reinterpret_cast<unsigned short*>(&l);
    }
    uint2 ph, pl;
    ph.x = (uint32_t)hb[0] | ((uint32_t)hb[1] << 16);
    ph.y = (uint32_t)hb[2] | ((uint32_t)hb[3] << 16);
    pl.x = (uint32_t)lb[0] | ((uint32_t)lb[1] << 16);
    pl.y = (uint32_t)lb[2] | ((uint32_t)lb[3] << 16);
    *(uint2*)(g_ahi + i) = ph;
    *(uint2*)(g_alo + i) = pl;
}

// transpose + split input_kernel W[256,384] -> [384,256]
__global__ __launch_bounds__(256) void convert_b(const float* __restrict__ W) {
    int n = blockIdx.x;
    int k = threadIdx.x;
    float v = W[(size_t)k * GG + n];
    __nv_bfloat16 h = __float2bfloat16(v);
    __nv_bfloat16 l = __float2bfloat16(v - __bfloat162float(h));
    g_bhi[(size_t)n * DD + k] = h;
    g_blo[(size_t)n * DD + k] = l;
}

// transpose recurrent_kernel rk[128,384] -> bf16 [384,128]
__global__ __launch_bounds__(128) void convert_rk(const float* __restrict__ rk) {
    int n = blockIdx.x;
    int k = threadIdx.x;
    g_rk[(size_t)n * UU + k] = __float2bfloat16(rk[(size_t)k * GG + n]);
}

// ---------------------------------------------------------------------------
// HMMA GEMM: g_xproj[M,384] = A[M,256] @ W[256,384], 3-way bf16 split.
// grid: x = N-tile (3, inner -> shares A via L2), y = (chunk, batch) tile:
//   row0 = (y & 255)*1024 + (y >> 8)*128  -> chunk-major production order so
// the scan's chunk 0 (all batches) is produced first. Epilogue signals
// g_flags[y] (3 arrivals = all N-tiles of that (chunk,batch) done).
// ---------------------------------------------------------------------------
#define GEMM_SMEM (2 * 4 * 16384)

__device__ __forceinline__ void load_tiles(uint32_t sb, int buf, int k0,
                                           int row0, int n0g, int tid) {
    const uint32_t base = sb + buf * 65536;
#pragma unroll
    for (int i = 0; i < 4; ++i) {
        const int id  = tid + i * 256;
        const int row = id >> 3;
        const int c16 = id & 7;
        const uint32_t so = SW128((uint32_t)(row * 128 + c16 * 16));
        const size_t aoff = (size_t)(row0 + row) * DD + k0 + c16 * 8;
        const size_t boff = (size_t)(n0g + row) * DD + k0 + c16 * 8;
        cp16(base + so,         g_ahi + aoff);
        cp16(base + 16384 + so, g_alo + aoff);
        cp16(base + 32768 + so, g_bhi + boff);
        cp16(base + 49152 + so, g_blo + boff);
    }
}

__global__ __launch_bounds__(256, 1) void gemm_mma() {
    extern __shared__ char gsm[];
    const uint32_t sb = s2u(gsm);

    const int tid  = threadIdx.x;
    const int wid  = tid >> 5;
    const int lane = tid & 31;
    const int n0g  = blockIdx.x * 128;
    const int row0 = (blockIdx.y & 255) * 1024 + (blockIdx.y >> 8) * 128;

    const int m0w = (wid >> 2) * 64;
    const int n0w = (wid & 3) * 32;

    float acc[4][4][4];
#pragma unroll
    for (int i = 0; i < 4; ++i)
#pragma unroll
        for (int j = 0; j < 4; ++j)
#pragma unroll
            for (int k = 0; k < 4; ++k) acc[i][j][k] = 0.f;

    const int a_lr = lane & 15;
    const int a_lc = (lane >> 4) * 16;
    const int b_lr = ((lane >> 4) << 3) + (lane & 7);
    const int b_lc = ((lane >> 3) & 1) * 16;

    load_tiles(sb, 0, 0, row0, n0g, tid);
    cp_commit();

#pragma unroll
    for (int c = 0; c < 4; ++c) {
        if (c < 3) {
            load_tiles(sb, (c + 1) & 1, (c + 1) * 64, row0, n0g, tid);
            cp_commit();
            cp_wait<1>();
        } else {
            cp_wait<0>();
        }
        __syncthreads();

        const uint32_t ab  = sb + (c & 1) * 65536;
        const uint32_t alb = ab + 16384;
        const uint32_t bhb = ab + 32768;
        const uint32_t blb = ab + 49152;

#pragma unroll
        for (int kf = 0; kf < 4; ++kf) {
            uint32_t ah[4][4], al[4][4], bh[2][4], bl[2][4];
#pragma unroll
            for (int mf = 0; mf < 4; ++mf) {
                const uint32_t off =
                    SW128((uint32_t)((m0w + mf * 16 + a_lr) * 128 + kf * 32 + a_lc));
                ldsm_x4(ah[mf], ab + off);
                ldsm_x4(al[mf], alb + off);
            }
#pragma unroll
            for (int nf2 = 0; nf2 < 2; ++nf2) {
                const uint32_t off =
                    SW128((uint32_t)((n0w + nf2 * 16 + b_lr) * 128 + kf * 32 + b_lc));
                ldsm_x4(bh[nf2], bhb + off);
                ldsm_x4(bl[nf2], blb + off);
            }
#pragma unroll
            for (int mf = 0; mf < 4; ++mf)
#pragma unroll
                for (int nf = 0; nf < 4; ++nf) {
                    const uint32_t* bhp = &bh[nf >> 1][(nf & 1) * 2];
                    const uint32_t* blp = &bl[nf >> 1][(nf & 1) * 2];
                    mma_bf16(acc[mf][nf], ah[mf], bhp);
                    mma_bf16(acc[mf][nf], ah[mf], blp);
                    mma_bf16(acc[mf][nf], al[mf], bhp);
                }
        }
        __syncthreads();
    }

#pragma unroll
    for (int mf = 0; mf < 4; ++mf) {
        const int rg = row0 + m0w + mf * 16 + (lane >> 2);
#pragma unroll
        for (int nf = 0; nf < 4; ++nf) {
            const int cg = n0g + n0w + nf * 8 + ((lane & 3) << 1);
            *(float2*)&g_xproj[(size_t)rg * GG + cg] =
                make_float2(acc[mf][nf][0], acc[mf][nf][1]);
            *(float2*)&g_xproj[(size_t)(rg + 8) * GG + cg] =
                make_float2(acc[mf][nf][2], acc[mf][nf][3]);
        }
    }

    // signal (chunk, batch) tile ready
    __syncthreads();
    if (tid == 0) {
        __threadfence();
        atomicAdd(&g_flags[blockIdx.y], 1);
    }
}

// ---------------------------------------------------------------------------
// forget gates: block = 64 bt rows; sig tile in smem, fk column in registers.
// ---------------------------------------------------------------------------
__global__ __launch_bounds__(256) void fgate_kernel(const float* __restrict__ sig,
                                                    const float* __restrict__ fk,
                                                    const float* __restrict__ bias) {
    __shared__ float ss[64 * 20];
    const int tid = threadIdx.x;
    const int bt0 = blockIdx.x * 64;

    for (int i = tid; i < 64 * 20; i += 256)
        ss[i] = sig[(size_t)bt0 * 20 + i];

    const int u    = tid & 127;
    const int bsub = tid >> 7;

    float wk[20];
#pragma unroll
    for (int k = 0; k < 20; ++k) wk[k] = __ldg(&fk[k * UU + u]);
    const float bf = bias[UU + u];

    __syncthreads();

#pragma unroll 4
    for (int i = 0; i < 32; ++i) {
        const int bt = bsub * 32 + i;
        float s = bf;
        const float* sr = ss + bt * 20;
#pragma unroll
        for (int k = 0; k < 20; ++k) s = fmaf(sr[k], wk[k], s);
        g_fg[(size_t)(bt0 + bt) * UU + u] = fsig(s);
    }
}

// ---------------------------------------------------------------------------
// HMMA scan (round-9 structure) + chunked flag waits so it can run
// concurrently with the producing GEMM.
// ---------------------------------------------------------------------------
#define XS_ROW 388
#define XS_F   (8 * XS_ROW)  // 3104
#define FS_ROW 132
#define FS_F   (8 * FS_ROW)  // 1056
#define AS_ROW 144           // words per batch row
#define AS_W   (8 * AS_ROW)  // 1152 u32 per buffer
#define XS_OFF 0
#define FS_OFF (2 * XS_F)
#define AS_OFF (2 * XS_F + 2 * FS_F)
#define SCAN_F (AS_OFF + 2 * AS_W)

__device__ __forceinline__ void wait_chunk(int c, int b0g, int tid) {
    if (tid < 8) {
        volatile int* f = (volatile int*)&g_flags[c * 256 + b0g + tid];
        while (*f < 3) {}
        __threadfence();
    }
}

__global__ __launch_bounds__(256, 1) void scan_mma(const float* __restrict__ bias,
                                                   float* __restrict__ out) {
    __shared__ __align__(16) float sm[SCAN_F];
    float* xs = sm + XS_OFF;
    float* fs = sm + FS_OFF;
    uint32_t* As = (uint32_t*)(sm + AS_OFF);
    const uint32_t smu = s2u(sm);

    const int tid  = threadIdx.x;
    const int wid  = tid >> 5;
    const int lane = tid & 31;
    const int b0g  = blockIdx.x * 8;

    for (int i = tid; i < 2 * AS_W; i += 256) As[i] = 0;

    // rk B-fragments: col n = (nc>>1)*128 + wid*16 + (nc&1)*8 + (lane>>2)
    uint32_t wfr[8][6][2];
#pragma unroll
    for (int kc = 0; kc < 8; ++kc)
#pragma unroll
        for (int nc = 0; nc < 6; ++nc) {
            const int n = (nc >> 1) * 128 + wid * 16 + (nc & 1) * 8 + (lane >> 2);
            const int k = kc * 16 + (lane & 3) * 2;
            wfr[kc][nc][0] = *(const uint32_t*)&g_rk[(size_t)n * UU + k];
            wfr[kc][nc][1] = *(const uint32_t*)&g_rk[(size_t)n * UU + k + 8];
        }

    float bb0[6], bb1[6], pp[6];
#pragma unroll
    for (int nc = 0; nc < 6; ++nc) {
        const int c = (nc >> 1) * 128 + wid * 16 + (nc & 1) * 8 + (lane & 3) * 2;
        bb0[nc] = (c < UU) ? bias[c] : bias[c + UU];
        bb1[nc] = (c + 1 < UU) ? bias[c + 1] : bias[c + 1 + UU];
        pp[nc]  = ((nc >> 1) == 1) ? 1.0f : 0.5f;
    }

    float cst[4] = {0.f, 0.f, 0.f, 0.f};   // c for u0,u1,u8,u9

#define PREFETCH(t)                                                            \
    {                                                                          \
        const int _buf = (t) & 1;                                              \
        _Pragma("unroll")                                                      \
        for (int k2 = 0; k2 < 3; ++k2) {                                       \
            const int id = tid + k2 * 256;                                     \
            const int r = id / 96, o = id % 96;                                \
            cp16(smu + (XS_OFF + _buf * XS_F + r * XS_ROW + o * 4) * 4,        \
                 &g_xproj[((size_t)(b0g + r) * TT + (t)) * GG + o * 4]);       \
        }                                                                      \
        cp16(smu + (FS_OFF + ((t) & 1) * FS_F + (tid >> 5) * FS_ROW +          \
                    (tid & 31) * 4) * 4,                                       \
             &g_fg[((size_t)(b0g + (tid >> 5)) * TT + (t)) * UU +              \
                   (tid & 31) * 4]);                                           \
        cp_commit();                                                           \
    }

    // wait for chunk 0 of this block's batches, then start the pipeline
    wait_chunk(0, b0g, tid);
    __syncthreads();
    PREFETCH(0);

    const int brow = lane >> 2;
    const int q4   = (lane & 3) * 4;
    const int ucol = wid * 16 + (lane & 3) * 2;

    for (int t = 0; t < TT; ++t) {
        cp_wait<0>();
        __syncthreads();   // x/f(t) ready; all warps finished iter t-1

        const uint32_t* Ar = As + (t & 1) * AS_W;        // h(t-1)
        uint32_t* Aw = As + ((t + 1) & 1) * AS_W;        // h(t)

        // acc init from x_proj
        const float* xb = xs + (t & 1) * XS_F + brow * XS_ROW;
        float acc[6][4];
#pragma unroll
        for (int nc = 0; nc < 6; ++nc) {
            const float2 xv =
                *(const float2*)&xb[(nc >> 1) * 128 + ucol + (nc & 1) * 8];
            acc[nc][0] = xv.x; acc[nc][1] = xv.y;
            acc[nc][2] = 0.f;  acc[nc][3] = 0.f;
        }

        if (t + 1 < TT) {
            if (((t + 1) & 127) == 0) {     // entering a new chunk
                wait_chunk((t + 1) >> 7, b0g, tid);
                __syncthreads();
            }
            PREFETCH(t + 1);
        }

        // gates = [h_hi; h_lo] @ rk  (A-fragment = one LDS.128 per kc)
#pragma unroll
        for (int kc = 0; kc < 8; ++kc) {
            const uint4 av = *(const uint4*)&Ar[brow * AS_ROW + kc * 16 + q4];
            uint32_t af[4] = {av.x, av.y, av.z, av.w};
#pragma unroll
            for (int nc = 0; nc < 6; ++nc)
                mma_bf16(acc[nc], af, wfr[kc][nc]);
        }

        // fold + bias + activation, all in registers
        float gv[6][2];
#pragma unroll
        for (int nc = 0; nc < 6; ++nc) {
            const float p = pp[nc], q = 1.0f - p;
            const float g0 = acc[nc][0] + acc[nc][2] + bb0[nc];
            const float g1 = acc[nc][1] + acc[nc][3] + bb1[nc];
            gv[nc][0] = fmaf(tanh_apx(g0 * p), p, q);
            gv[nc][1] = fmaf(tanh_apx(g1 * p), p, q);
        }

        // in-register combine for (batch=brow, u = ucol+{0,1,8,9})
        const float* fr = fs + (t & 1) * FS_F + brow * FS_ROW + ucol;
        const float2 fA = *(const float2*)&fr[0];
        const float2 fB = *(const float2*)&fr[8];
        cst[0] = fmaf(fA.x, cst[0], gv[0][0] * gv[2][0]);
        cst[1] = fmaf(fA.y, cst[1], gv[0][1] * gv[2][1]);
        cst[2] = fmaf(fB.x, cst[2], gv[1][0] * gv[3][0]);
        cst[3] = fmaf(fB.y, cst[3], gv[1][1] * gv[3][1]);
        const float h0 = gv[4][0] * tanh_apx(cst[0]);
        const float h1 = gv[4][1] * tanh_apx(cst[1]);
        const float h2 = gv[5][0] * tanh_apx(cst[2]);
        const float h3 = gv[5][1] * tanh_apx(cst[3]);

        float* orow = &out[((size_t)(b0g + brow) * TT + t) * UU + ucol];
        *(float2*)&orow[0] = make_float2(h0, h1);
        *(float2*)&orow[8] = make_float2(h2, h3);

        // write h(t) as one 16B fragment {hi(2q), lo(2q), hi(2q+8), lo(2q+8)}
        const __nv_bfloat16 h0h = __float2bfloat16(h0);
        const __nv_bfloat16 h1h = __float2bfloat16(h1);
        const __nv_bfloat16 h2h = __float2bfloat16(h2);
        const __nv_bfloat16 h3h = __float2bfloat16(h3);
        const __nv_bfloat16 h0l = __float2bfloat16(h0 - __bfloat162float(h0h));
        const __nv_bfloat16 h1l = __float2bfloat16(h1 - __bfloat162float(h1h));
        const __nv_bfloat16 h2l = __float2bfloat16(h2 - __bfloat162float(h2h));
        const __nv_bfloat16 h3l = __float2bfloat16(h3 - __bfloat162float(h3h));
        uint4 frag;
        frag.x = (uint32_t)*(const unsigned short*)&h0h |
                 ((uint32_t)*(const unsigned short*)&h1h << 16);
        frag.y = (uint32_t)*(const unsigned short*)&h0l |
                 ((uint32_t)*(const unsigned short*)&h1l << 16);
        frag.z = (uint32_t)*(const unsigned short*)&h2h |
                 ((uint32_t)*(const unsigned short*)&h3h << 16);
        frag.w = (uint32_t)*(const unsigned short*)&h2l |
                 ((uint32_t)*(const unsigned short*)&h3l << 16);
        *(uint4*)&Aw[brow * AS_ROW + wid * 16 + q4] = frag;
    }
}

// ---------------------------------------------------------------------------
extern "C" void kernel_launch(void* const* d_in, const int* in_sizes, int n_in,
                              void* d_out, int out_size) {
    const float* inputs     = (const float*)d_in[0];
    const float* signatures = (const float*)d_in[1];
    const float* ikern      = (const float*)d_in[2];
    const float* rkern      = (const float*)d_in[3];
    const float* fkern      = (const float*)d_in[4];
    const float* bias       = (const float*)d_in[5];
    float* out = (float*)d_out;

    (void)in_sizes; (void)n_in; (void)out_size;

    // one-time resources (host-side only; no device allocations)
    static cudaStream_t s2 = nullptr;
    static cudaEvent_t evFork = nullptr, evJoin = nullptr;
    if (s2 == nullptr) {
        cudaStreamCreateWithFlags(&s2, cudaStreamNonBlocking);
        cudaEventCreateWithFlags(&evFork, cudaEventDisableTiming);
        cudaEventCreateWithFlags(&evJoin, cudaEventDisableTiming);
        cudaFuncSetAttribute(gemm_mma,
                             cudaFuncAttributeMaxDynamicSharedMemorySize,
                             GEMM_SMEM);
    }

    // flags must be zero before gemm increments and scan polls
    zero_flags<<<8, 256>>>();
    cudaEventRecord(evFork, 0);
    cudaStreamWaitEvent(s2, evFork, 0);

    // branch A (default stream): produce x_proj, chunk-major
    convert_a<<<(MM * DD) / 4 / 256, 256>>>(inputs);
    convert_b<<<GG, DD>>>(ikern);
    gemm_mma<<<dim3(GG / 128, MM / 128), 256, GEMM_SMEM>>>();

    // branch B (s2): consume x_proj as it becomes ready
    convert_rk<<<GG, UU, 0, s2>>>(rkern);
    fgate_kernel<<<MM / 64, 256, 0, s2>>>(signatures, fkern, bias);
    scan_mma<<<BB / 8, 256, 0, s2>>>(bias, out);

    cudaEventRecord(evJoin, s2);
    cudaStreamWaitEvent(0, evJoin, 0);
}

// round 12
// speedup vs baseline: 1.3380x; 1.3380x over previous
#include <cuda_runtime.h>
#include <cuda_bf16.h>
#include <math.h>
#include <stdint.h>

// Problem constants
#define BB   256
#define TT   1024
#define DD   256
#define UU   128
#define GG   384      // 3*U
#define MM   (BB*TT)  // 262144 rows

#define NBLK  148
#define NSCAN 32
#define NWORK (NBLK - NSCAN)   // 116
#define NTILE 6144             // 3 N-tiles x 2048 (chunk,batch) tiles

// Scratch (device globals — no allocation allowed)
__device__ float g_xproj[(size_t)MM * GG];        // [B*T, 384]
__device__ float g_fg[(size_t)MM * UU];           // [B*T, 128]
__device__ __nv_bfloat16 g_bhi[(size_t)GG * DD];  // W^T hi: [384,256]
__device__ __nv_bfloat16 g_blo[(size_t)GG * DD];  // W^T lo
__device__ __nv_bfloat16 g_rk[(size_t)GG * UU];   // rk^T bf16 hi: [384,128]
__device__ int g_flags[8 * 256];                  // [chunk][batch] -> 3 = ready

// ---------------------------------------------------------------------------
__device__ __forceinline__ uint32_t s2u(const void* p) {
    uint32_t a;
    asm("{ .reg .u64 t; cvta.to.shared.u64 t, %1; cvt.u32.u64 %0, t; }"
        : "=r"(a) : "l"(p));
    return a;
}

#define SW128(o) ((o) ^ (((o) >> 3) & 0x70))

__device__ __forceinline__ void ldsm_x4(uint32_t* r, uint32_t addr) {
    asm volatile("ldmatrix.sync.aligned.m8n8.x4.shared.b16 {%0,%1,%2,%3}, [%4];"
                 : "=r"(r[0]), "=r"(r[1]), "=r"(r[2]), "=r"(r[3]) : "r"(addr));
}

__device__ __forceinline__ void mma_bf16(float* d, const uint32_t* a,
                                         const uint32_t* b) {
    asm volatile(
        "mma.sync.aligned.m16n8k16.row.col.f32.bf16.bf16.f32 "
        "{%0,%1,%2,%3}, {%4,%5,%6,%7}, {%8,%9}, {%0,%1,%2,%3};"
        : "+f"(d[0]), "+f"(d[1]), "+f"(d[2]), "+f"(d[3])
        : "r"(a[0]), "r"(a[1]), "r"(a[2]), "r"(a[3]), "r"(b[0]), "r"(b[1]));
}

__device__ __forceinline__ void cp16(uint32_t dst, const void* src) {
    asm volatile("cp.async.cg.shared.global [%0], [%1], 16;"
                 :: "r"(dst), "l"(src) : "memory");
}
__device__ __forceinline__ void cp_commit() {
    asm volatile("cp.async.commit_group;" ::: "memory");
}
template <int N>
__device__ __forceinline__ void cp_wait() {
    asm volatile("cp.async.wait_group %0;" :: "n"(N) : "memory");
}

__device__ __forceinline__ float tanh_apx(float x) {
    float y;
    asm("tanh.approx.f32 %0, %1;" : "=f"(y) : "f"(x));
    return y;
}
__device__ __forceinline__ float fsig(float x) {
    return __fdividef(1.0f, 1.0f + __expf(-x));
}

__device__ __forceinline__ uint32_t pack_hi2(float a, float b) {
    const __nv_bfloat16 ha = __float2bfloat16(a);
    const __nv_bfloat16 hb = __float2bfloat16(b);
    return (uint32_t)*(const unsigned short*)&ha |
           ((uint32_t)*(const unsigned short*)&hb << 16);
}
__device__ __forceinline__ uint32_t pack_lo2(float a, float b) {
    const __nv_bfloat16 ha = __float2bfloat16(a);
    const __nv_bfloat16 hb = __float2bfloat16(b);
    const __nv_bfloat16 la = __float2bfloat16(a - __bfloat162float(ha));
    const __nv_bfloat16 lb = __float2bfloat16(b - __bfloat162float(hb));
    return (uint32_t)*(const unsigned short*)&la |
           ((uint32_t)*(const unsigned short*)&lb << 16);
}

// ---------------------------------------------------------------------------
__global__ void zero_flags() {
    g_flags[blockIdx.x * 256 + threadIdx.x] = 0;
}

// transpose + split input_kernel W[256,384] -> [384,256]
__global__ __launch_bounds__(256) void convert_b(const float* __restrict__ W) {
    int n = blockIdx.x;
    int k = threadIdx.x;
    float v = W[(size_t)k * GG + n];
    __nv_bfloat16 h = __float2bfloat16(v);
    __nv_bfloat16 l = __float2bfloat16(v - __bfloat162float(h));
    g_bhi[(size_t)n * DD + k] = h;
    g_blo[(size_t)n * DD + k] = l;
}

// transpose recurrent_kernel rk[128,384] -> bf16 [384,128]
__global__ __launch_bounds__(128) void convert_rk(const float* __restrict__ rk) {
    int n = blockIdx.x;
    int k = threadIdx.x;
    g_rk[(size_t)n * UU + k] = __float2bfloat16(rk[(size_t)k * GG + n]);
}

// forget gates: block = 64 bt rows; sig tile in smem, fk column in registers.
__global__ __launch_bounds__(256) void fgate_kernel(const float* __restrict__ sig,
                                                    const float* __restrict__ fk,
                                                    const float* __restrict__ bias) {
    __shared__ float ss[64 * 20];
    const int tid = threadIdx.x;
    const int bt0 = blockIdx.x * 64;

    for (int i = tid; i < 64 * 20; i += 256)
        ss[i] = sig[(size_t)bt0 * 20 + i];

    const int u    = tid & 127;
    const int bsub = tid >> 7;

    float wk[20];
#pragma unroll
    for (int k = 0; k < 20; ++k) wk[k] = __ldg(&fk[k * UU + u]);
    const float bf = bias[UU + u];

    __syncthreads();

#pragma unroll 4
    for (int i = 0; i < 32; ++i) {
        const int bt = bsub * 32 + i;
        float s = bf;
        const float* sr = ss + bt * 20;
#pragma unroll
        for (int k = 0; k < 20; ++k) s = fmaf(sr[k], wk[k], s);
        g_fg[(size_t)(bt0 + bt) * UU + u] = fsig(s);
    }
}

// ---------------------------------------------------------------------------
// GEMM worker tile (device fn). A loaded fp32 + split in-kernel; B from
// pre-split g_bhi/g_blo via cp.async. Same mma structure as before.
// smem per buffer: Ahi | Alo | Bhi | Blo, 16KB each; 2 buffers = 128KB.
// ---------------------------------------------------------------------------
#define MEGA_SMEM (2 * 4 * 16384)

__device__ __forceinline__ void ldA(const float* __restrict__ inputs, int row0,
                                    int k0, int tid, float4* fa) {
#pragma unroll
    for (int i = 0; i < 4; ++i) {
        const int u = tid + i * 256;
        const int row = u >> 3, c16 = u & 7;
        const float4* src =
            (const float4*)&inputs[(size_t)(row0 + row) * DD + k0 + c16 * 8];
        fa[2 * i]     = src[0];
        fa[2 * i + 1] = src[1];
    }
}

__device__ __forceinline__ void stA(char* dsm, uint32_t base, int tid,
                                    const float4* fa) {
#pragma unroll
    for (int i = 0; i < 4; ++i) {
        const int u = tid + i * 256;
        const int row = u >> 3, c16 = u & 7;
        const float4 a = fa[2 * i], b = fa[2 * i + 1];
        uint4 hi, lo;
        hi.x = pack_hi2(a.x, a.y); hi.y = pack_hi2(a.z, a.w);
        hi.z = pack_hi2(b.x, b.y); hi.w = pack_hi2(b.z, b.w);
        lo.x = pack_lo2(a.x, a.y); lo.y = pack_lo2(a.z, a.w);
        lo.z = pack_lo2(b.x, b.y); lo.w = pack_lo2(b.z, b.w);
        const uint32_t so = SW128((uint32_t)(row * 128 + c16 * 16));
        *(uint4*)(dsm + base + so)         = hi;
        *(uint4*)(dsm + base + 16384 + so) = lo;
    }
}

__device__ __forceinline__ void ldB(uint32_t sb, int buf, int k0, int n0g,
                                    int tid) {
    const uint32_t base = sb + buf * 65536;
#pragma unroll
    for (int i = 0; i < 4; ++i) {
        const int id  = tid + i * 256;
        const int row = id >> 3;
        const int c16 = id & 7;
        const uint32_t so = SW128((uint32_t)(row * 128 + c16 * 16));
        const size_t boff = (size_t)(n0g + row) * DD + k0 + c16 * 8;
        cp16(base + 32768 + so, g_bhi + boff);
        cp16(base + 49152 + so, g_blo + boff);
    }
}

__device__ void gemm_tile(char* dsm, const float* __restrict__ inputs,
                          int n0g, int y, int tid) {
    const uint32_t sb = s2u(dsm);
    const int wid  = tid >> 5;
    const int lane = tid & 31;
    const int row0 = (y & 255) * 1024 + (y >> 8) * 128;

    const int m0w = (wid >> 2) * 64;
    const int n0w = (wid & 3) * 32;

    float acc[4][4][4];
#pragma unroll
    for (int i = 0; i < 4; ++i)
#pragma unroll
        for (int j = 0; j < 4; ++j)
#pragma unroll
            for (int k = 0; k < 4; ++k) acc[i][j][k] = 0.f;

    const int a_lr = lane & 15;
    const int a_lc = (lane >> 4) * 16;
    const int b_lr = ((lane >> 4) << 3) + (lane & 7);
    const int b_lc = ((lane >> 3) & 1) * 16;

    // prologue: chunk 0
    {
        float4 fa[8];
        ldA(inputs, row0, 0, tid, fa);
        ldB(sb, 0, 0, n0g, tid);
        cp_commit();
        stA(dsm, 0, tid, fa);
        cp_wait<0>();
        __syncthreads();
    }

#pragma unroll
    for (int c = 0; c < 4; ++c) {
        float4 fa[8];
        if (c < 3) {
            ldA(inputs, row0, (c + 1) * 64, tid, fa);   // LDG early
            ldB(sb, (c + 1) & 1, (c + 1) * 64, n0g, tid);
            cp_commit();
        }

        const uint32_t ab  = sb + (c & 1) * 65536;
        const uint32_t alb = ab + 16384;
        const uint32_t bhb = ab + 32768;
        const uint32_t blb = ab + 49152;

#pragma unroll
        for (int kf = 0; kf < 4; ++kf) {
            uint32_t ah[4][4], al[4][4], bh[2][4], bl[2][4];
#pragma unroll
            for (int mf = 0; mf < 4; ++mf) {
                const uint32_t off =
                    SW128((uint32_t)((m0w + mf * 16 + a_lr) * 128 + kf * 32 + a_lc));
                ldsm_x4(ah[mf], ab + off);
                ldsm_x4(al[mf], alb + off);
            }
#pragma unroll
            for (int nf2 = 0; nf2 < 2; ++nf2) {
                const uint32_t off =
                    SW128((uint32_t)((n0w + nf2 * 16 + b_lr) * 128 + kf * 32 + b_lc));
                ldsm_x4(bh[nf2], bhb + off);
                ldsm_x4(bl[nf2], blb + off);
            }
#pragma unroll
            for (int mf = 0; mf < 4; ++mf)
#pragma unroll
                for (int nf = 0; nf < 4; ++nf) {
                    const uint32_t* bhp = &bh[nf >> 1][(nf & 1) * 2];
                    const uint32_t* blp = &bl[nf >> 1][(nf & 1) * 2];
                    mma_bf16(acc[mf][nf], ah[mf], bhp);
                    mma_bf16(acc[mf][nf], ah[mf], blp);
                    mma_bf16(acc[mf][nf], al[mf], bhp);
                }
        }

        if (c < 3) {
            __syncthreads();                 // all mma reads of buf^1 done
            stA(dsm, ((c + 1) & 1) * 65536, tid, fa);
            cp_wait<0>();
        }
        __syncthreads();
    }

#pragma unroll
    for (int mf = 0; mf < 4; ++mf) {
        const int rg = row0 + m0w + mf * 16 + (lane >> 2);
#pragma unroll
        for (int nf = 0; nf < 4; ++nf) {
            const int cg = n0g + n0w + nf * 8 + ((lane & 3) << 1);
            *(float2*)&g_xproj[(size_t)rg * GG + cg] =
                make_float2(acc[mf][nf][0], acc[mf][nf][1]);
            *(float2*)&g_xproj[(size_t)(rg + 8) * GG + cg] =
                make_float2(acc[mf][nf][2], acc[mf][nf][3]);
        }
    }

    __syncthreads();
    if (tid == 0) {
        __threadfence();
        atomicAdd(&g_flags[y], 1);
    }
}

// ---------------------------------------------------------------------------
// Scan (round-9 structure) with chunk flag waits — runs on bids 0..31.
// ---------------------------------------------------------------------------
#define XS_ROW 388
#define XS_F   (8 * XS_ROW)  // 3104
#define FS_ROW 132
#define FS_F   (8 * FS_ROW)  // 1056
#define AS_ROW 144
#define AS_W   (8 * AS_ROW)  // 1152 u32 per buffer
#define XS_OFF 0
#define FS_OFF (2 * XS_F)
#define AS_OFF (2 * XS_F + 2 * FS_F)
#define SCAN_F (AS_OFF + 2 * AS_W)

__device__ __forceinline__ void wait_chunk(int c, int b0g, int tid) {
    if (tid < 8) {
        volatile int* f = (volatile int*)&g_flags[c * 256 + b0g + tid];
        while (*f < 3) {}
        __threadfence();
    }
}

__device__ void scan_body(char* dsm, const float* __restrict__ bias,
                          float* __restrict__ out, int bid, int tid) {
    float* sm = (float*)dsm;
    float* xs = sm + XS_OFF;
    float* fs = sm + FS_OFF;
    uint32_t* As = (uint32_t*)(sm + AS_OFF);
    const uint32_t smu = s2u(sm);

    const int wid  = tid >> 5;
    const int lane = tid & 31;
    const int b0g  = bid * 8;

    for (int i = tid; i < 2 * AS_W; i += 256) As[i] = 0;

    uint32_t wfr[8][6][2];
#pragma unroll
    for (int kc = 0; kc < 8; ++kc)
#pragma unroll
        for (int nc = 0; nc < 6; ++nc) {
            const int n = (nc >> 1) * 128 + wid * 16 + (nc & 1) * 8 + (lane >> 2);
            const int k = kc * 16 + (lane & 3) * 2;
            wfr[kc][nc][0] = *(const uint32_t*)&g_rk[(size_t)n * UU + k];
            wfr[kc][nc][1] = *(const uint32_t*)&g_rk[(size_t)n * UU + k + 8];
        }

    float bb0[6], bb1[6], pp[6];
#pragma unroll
    for (int nc = 0; nc < 6; ++nc) {
        const int c = (nc >> 1) * 128 + wid * 16 + (nc & 1) * 8 + (lane & 3) * 2;
        bb0[nc] = (c < UU) ? bias[c] : bias[c + UU];
        bb1[nc] = (c + 1 < UU) ? bias[c + 1] : bias[c + 1 + UU];
        pp[nc]  = ((nc >> 1) == 1) ? 1.0f : 0.5f;
    }

    float cst[4] = {0.f, 0.f, 0.f, 0.f};

#define PREFETCH(t)                                                            \
    {                                                                          \
        const int _buf = (t) & 1;                                              \
        _Pragma("unroll")                                                      \
        for (int k2 = 0; k2 < 3; ++k2) {                                       \
            const int id = tid + k2 * 256;                                     \
            const int r = id / 96, o = id % 96;                                \
            cp16(smu + (XS_OFF + _buf * XS_F + r * XS_ROW + o * 4) * 4,        \
                 &g_xproj[((size_t)(b0g + r) * TT + (t)) * GG + o * 4]);       \
        }                                                                      \
        cp16(smu + (FS_OFF + ((t) & 1) * FS_F + (tid >> 5) * FS_ROW +          \
                    (tid & 31) * 4) * 4,                                       \
             &g_fg[((size_t)(b0g + (tid >> 5)) * TT + (t)) * UU +              \
                   (tid & 31) * 4]);                                           \
        cp_commit();                                                           \
    }

    wait_chunk(0, b0g, tid);
    __syncthreads();
    PREFETCH(0);

    const int brow = lane >> 2;
    const int q4   = (lane & 3) * 4;
    const int ucol = wid * 16 + (lane & 3) * 2;

    for (int t = 0; t < TT; ++t) {
        cp_wait<0>();
        __syncthreads();

        const uint32_t* Ar = As + (t & 1) * AS_W;
        uint32_t* Aw = As + ((t + 1) & 1) * AS_W;

        const float* xb = xs + (t & 1) * XS_F + brow * XS_ROW;
        float acc[6][4];
#pragma unroll
        for (int nc = 0; nc < 6; ++nc) {
            const float2 xv =
                *(const float2*)&xb[(nc >> 1) * 128 + ucol + (nc & 1) * 8];
            acc[nc][0] = xv.x; acc[nc][1] = xv.y;
            acc[nc][2] = 0.f;  acc[nc][3] = 0.f;
        }

        if (t + 1 < TT) {
            if (((t + 1) & 127) == 0) {
                wait_chunk((t + 1) >> 7, b0g, tid);
                __syncthreads();
            }
            PREFETCH(t + 1);
        }

#pragma unroll
        for (int kc = 0; kc < 8; ++kc) {
            const uint4 av = *(const uint4*)&Ar[brow * AS_ROW + kc * 16 + q4];
            uint32_t af[4] = {av.x, av.y, av.z, av.w};
#pragma unroll
            for (int nc = 0; nc < 6; ++nc)
                mma_bf16(acc[nc], af, wfr[kc][nc]);
        }

        float gv[6][2];
#pragma unroll
        for (int nc = 0; nc < 6; ++nc) {
            const float p = pp[nc], q = 1.0f - p;
            const float g0 = acc[nc][0] + acc[nc][2] + bb0[nc];
            const float g1 = acc[nc][1] + acc[nc][3] + bb1[nc];
            gv[nc][0] = fmaf(tanh_apx(g0 * p), p, q);
            gv[nc][1] = fmaf(tanh_apx(g1 * p), p, q);
        }

        const float* fr = fs + (t & 1) * FS_F + brow * FS_ROW + ucol;
        const float2 fA = *(const float2*)&fr[0];
        const float2 fB = *(const float2*)&fr[8];
        cst[0] = fmaf(fA.x, cst[0], gv[0][0] * gv[2][0]);
        cst[1] = fmaf(fA.y, cst[1], gv[0][1] * gv[2][1]);
        cst[2] = fmaf(fB.x, cst[2], gv[1][0] * gv[3][0]);
        cst[3] = fmaf(fB.y, cst[3], gv[1][1] * gv[3][1]);
        const float h0 = gv[4][0] * tanh_apx(cst[0]);
        const float h1 = gv[4][1] * tanh_apx(cst[1]);
        const float h2 = gv[5][0] * tanh_apx(cst[2]);
        const float h3 = gv[5][1] * tanh_apx(cst[3]);

        float* orow = &out[((size_t)(b0g + brow) * TT + t) * UU + ucol];
        *(float2*)&orow[0] = make_float2(h0, h1);
        *(float2*)&orow[8] = make_float2(h2, h3);

        uint4 frag;
        frag.x = pack_hi2(h0, h1);
        frag.y = pack_lo2(h0, h1);
        frag.z = pack_hi2(h2, h3);
        frag.w = pack_lo2(h2, h3);
        *(uint4*)&Aw[brow * AS_ROW + wid * 16 + q4] = frag;
    }
}

// ---------------------------------------------------------------------------
// Megakernel: one wave of 148 CTAs (128KB smem => 1/SM).
// bids [0,32): scan. bids [32,148): gemm workers, chunk-major tile order.
// ---------------------------------------------------------------------------
__global__ __launch_bounds__(256, 1)
void mega_kernel(const float* __restrict__ inputs,
                 const float* __restrict__ bias,
                 float* __restrict__ out) {
    extern __shared__ __align__(16) char dsm[];
    const int bid = blockIdx.x;
    const int tid = threadIdx.x;

    if (bid < NSCAN) {
        scan_body(dsm, bias, out, bid, tid);
    } else {
        for (int tau = bid - NSCAN; tau < NTILE; tau += NWORK) {
            const int n0g = (tau % 3) * 128;
            const int y   = tau / 3;
            gemm_tile(dsm, inputs, n0g, y, tid);
        }
    }
}

// ---------------------------------------------------------------------------
extern "C" void kernel_launch(void* const* d_in, const int* in_sizes, int n_in,
                              void* d_out, int out_size) {
    const float* inputs     = (const float*)d_in[0];
    const float* signatures = (const float*)d_in[1];
    const float* ikern      = (const float*)d_in[2];
    const float* rkern      = (const float*)d_in[3];
    const float* fkern      = (const float*)d_in[4];
    const float* bias       = (const float*)d_in[5];
    float* out = (float*)d_out;

    (void)in_sizes; (void)n_in; (void)out_size;

    static bool init = false;
    if (!init) {
        cudaFuncSetAttribute(mega_kernel,
                             cudaFuncAttributeMaxDynamicSharedMemorySize,
                             MEGA_SMEM);
        init = true;
    }

    zero_flags<<<8, 256>>>();
    convert_b<<<GG, DD>>>(ikern);
    convert_rk<<<GG, UU>>>(rkern);
    fgate_kernel<<<MM / 64, 256>>>(signatures, fkern, bias);
    mega_kernel<<<NBLK, 256, MEGA_SMEM>>>(inputs, bias, out);
}

// round 13
// speedup vs baseline: 1.3918x; 1.0402x over previous
#include <cuda_runtime.h>
#include <cuda_bf16.h>
#include <math.h>
#include <stdint.h>

// Problem constants
#define BB   256
#define TT   1024
#define DD   256
#define UU   128
#define GG   384      // 3*U
#define MM   (BB*TT)  // 262144 rows

#define NBLK  148
#define NSCAN 32
#define NWORK (NBLK - NSCAN)   // 116
#define NJOB  8192             // 8 chunks x 256 batches x (3 gemm + 1 fgate)

// Scratch (device globals — no allocation allowed)
__device__ float g_xproj[(size_t)MM * GG];        // [B*T, 384]
__device__ float g_fg[(size_t)MM * UU];           // [B*T, 128]
__device__ __nv_bfloat16 g_bhi[(size_t)GG * DD];  // W^T hi: [384,256]
__device__ __nv_bfloat16 g_blo[(size_t)GG * DD];  // W^T lo
__device__ __nv_bfloat16 g_rk[(size_t)GG * UU];   // rk^T bf16 hi: [384,128]
__device__ int g_flags[8 * 256];                  // [chunk][batch] -> 4 = ready

// ---------------------------------------------------------------------------
__device__ __forceinline__ uint32_t s2u(const void* p) {
    uint32_t a;
    asm("{ .reg .u64 t; cvta.to.shared.u64 t, %1; cvt.u32.u64 %0, t; }"
        : "=r"(a) : "l"(p));
    return a;
}

#define SW128(o) ((o) ^ (((o) >> 3) & 0x70))

__device__ __forceinline__ void ldsm_x4(uint32_t* r, uint32_t addr) {
    asm volatile("ldmatrix.sync.aligned.m8n8.x4.shared.b16 {%0,%1,%2,%3}, [%4];"
                 : "=r"(r[0]), "=r"(r[1]), "=r"(r[2]), "=r"(r[3]) : "r"(addr));
}

__device__ __forceinline__ void mma_bf16(float* d, const uint32_t* a,
                                         const uint32_t* b) {
    asm volatile(
        "mma.sync.aligned.m16n8k16.row.col.f32.bf16.bf16.f32 "
        "{%0,%1,%2,%3}, {%4,%5,%6,%7}, {%8,%9}, {%0,%1,%2,%3};"
        : "+f"(d[0]), "+f"(d[1]), "+f"(d[2]), "+f"(d[3])
        : "r"(a[0]), "r"(a[1]), "r"(a[2]), "r"(a[3]), "r"(b[0]), "r"(b[1]));
}

__device__ __forceinline__ void cp16(uint32_t dst, const void* src) {
    asm volatile("cp.async.cg.shared.global [%0], [%1], 16;"
                 :: "r"(dst), "l"(src) : "memory");
}
__device__ __forceinline__ void cp_commit() {
    asm volatile("cp.async.commit_group;" ::: "memory");
}
template <int N>
__device__ __forceinline__ void cp_wait() {
    asm volatile("cp.async.wait_group %0;" :: "n"(N) : "memory");
}

__device__ __forceinline__ float tanh_apx(float x) {
    float y;
    asm("tanh.approx.f32 %0, %1;" : "=f"(y) : "f"(x));
    return y;
}
__device__ __forceinline__ float fsig(float x) {
    return __fdividef(1.0f, 1.0f + __expf(-x));
}

__device__ __forceinline__ uint32_t pack_hi2(float a, float b) {
    const __nv_bfloat16 ha = __float2bfloat16(a);
    const __nv_bfloat16 hb = __float2bfloat16(b);
    return (uint32_t)*(const unsigned short*)&ha |
           ((uint32_t)*(const unsigned short*)&hb << 16);
}
__device__ __forceinline__ uint32_t pack_lo2(float a, float b) {
    const __nv_bfloat16 ha = __float2bfloat16(a);
    const __nv_bfloat16 hb = __float2bfloat16(b);
    const __nv_bfloat16 la = __float2bfloat16(a - __bfloat162float(ha));
    const __nv_bfloat16 lb = __float2bfloat16(b - __bfloat162float(hb));
    return (uint32_t)*(const unsigned short*)&la |
           ((uint32_t)*(const unsigned short*)&lb << 16);
}

// ---------------------------------------------------------------------------
__global__ void zero_flags() {
    g_flags[blockIdx.x * 256 + threadIdx.x] = 0;
}

// transpose + split input_kernel W[256,384] -> [384,256]
__global__ __launch_bounds__(256) void convert_b(const float* __restrict__ W) {
    int n = blockIdx.x;
    int k = threadIdx.x;
    float v = W[(size_t)k * GG + n];
    __nv_bfloat16 h = __float2bfloat16(v);
    __nv_bfloat16 l = __float2bfloat16(v - __bfloat162float(h));
    g_bhi[(size_t)n * DD + k] = h;
    g_blo[(size_t)n * DD + k] = l;
}

// transpose recurrent_kernel rk[128,384] -> bf16 [384,128]
__global__ __launch_bounds__(128) void convert_rk(const float* __restrict__ rk) {
    int n = blockIdx.x;
    int k = threadIdx.x;
    g_rk[(size_t)n * UU + k] = __float2bfloat16(rk[(size_t)k * GG + n]);
}

// ---------------------------------------------------------------------------
// GEMM worker tile (512 threads, 16 warps x 32x32 warp tiles).
// smem: 2 buffers x (Ahi|Alo|Bhi|Blo, 16KB each) = 128KB; sig region at 128KB.
// ---------------------------------------------------------------------------
#define FK_OFF 131072
#define MEGA_SMEM (FK_OFF + 128 * 20 * 4)

__device__ __forceinline__ void ldA(const float* __restrict__ inputs, int row0,
                                    int k0, int tid, float4* fa) {
#pragma unroll
    for (int i = 0; i < 2; ++i) {
        const int u = tid + i * 512;
        const int row = u >> 3, c16 = u & 7;
        const float4* src =
            (const float4*)&inputs[(size_t)(row0 + row) * DD + k0 + c16 * 8];
        fa[2 * i]     = src[0];
        fa[2 * i + 1] = src[1];
    }
}

__device__ __forceinline__ void stA(char* dsm, uint32_t base, int tid,
                                    const float4* fa) {
#pragma unroll
    for (int i = 0; i < 2; ++i) {
        const int u = tid + i * 512;
        const int row = u >> 3, c16 = u & 7;
        const float4 a = fa[2 * i], b = fa[2 * i + 1];
        uint4 hi, lo;
        hi.x = pack_hi2(a.x, a.y); hi.y = pack_hi2(a.z, a.w);
        hi.z = pack_hi2(b.x, b.y); hi.w = pack_hi2(b.z, b.w);
        lo.x = pack_lo2(a.x, a.y); lo.y = pack_lo2(a.z, a.w);
        lo.z = pack_lo2(b.x, b.y); lo.w = pack_lo2(b.z, b.w);
        const uint32_t so = SW128((uint32_t)(row * 128 + c16 * 16));
        *(uint4*)(dsm + base + so)         = hi;
        *(uint4*)(dsm + base + 16384 + so) = lo;
    }
}

__device__ __forceinline__ void ldB(uint32_t sb, int buf, int k0, int n0g,
                                    int tid) {
    const uint32_t base = sb + buf * 65536;
#pragma unroll
    for (int i = 0; i < 2; ++i) {
        const int id  = tid + i * 512;
        const int row = id >> 3;
        const int c16 = id & 7;
        const uint32_t so = SW128((uint32_t)(row * 128 + c16 * 16));
        const size_t boff = (size_t)(n0g + row) * DD + k0 + c16 * 8;
        cp16(base + 32768 + so, g_bhi + boff);
        cp16(base + 49152 + so, g_blo + boff);
    }
}

__device__ void gemm_tile(char* dsm, const float* __restrict__ inputs,
                          int n0g, int row0, int tid) {
    const uint32_t sb = s2u(dsm);
    const int wid  = tid >> 5;
    const int lane = tid & 31;

    const int m0w = (wid >> 2) * 32;   // 0,32,64,96
    const int n0w = (wid & 3) * 32;

    float acc[2][4][4];
#pragma unroll
    for (int i = 0; i < 2; ++i)
#pragma unroll
        for (int j = 0; j < 4; ++j)
#pragma unroll
            for (int k = 0; k < 4; ++k) acc[i][j][k] = 0.f;

    const int a_lr = lane & 15;
    const int a_lc = (lane >> 4) * 16;
    const int b_lr = ((lane >> 4) << 3) + (lane & 7);
    const int b_lc = ((lane >> 3) & 1) * 16;

    {
        float4 fa[4];
        ldA(inputs, row0, 0, tid, fa);
        ldB(sb, 0, 0, n0g, tid);
        cp_commit();
        stA(dsm, 0, tid, fa);
        cp_wait<0>();
        __syncthreads();
    }

#pragma unroll
    for (int c = 0; c < 4; ++c) {
        float4 fa[4];
        if (c < 3) {
            ldA(inputs, row0, (c + 1) * 64, tid, fa);
            ldB(sb, (c + 1) & 1, (c + 1) * 64, n0g, tid);
            cp_commit();
        }

        const uint32_t ab  = sb + (c & 1) * 65536;
        const uint32_t alb = ab + 16384;
        const uint32_t bhb = ab + 32768;
        const uint32_t blb = ab + 49152;

#pragma unroll
        for (int kf = 0; kf < 4; ++kf) {
            uint32_t ah[2][4], al[2][4], bh[2][4], bl[2][4];
#pragma unroll
            for (int mf = 0; mf < 2; ++mf) {
                const uint32_t off =
                    SW128((uint32_t)((m0w + mf * 16 + a_lr) * 128 + kf * 32 + a_lc));
                ldsm_x4(ah[mf], ab + off);
                ldsm_x4(al[mf], alb + off);
            }
#pragma unroll
            for (int nf2 = 0; nf2 < 2; ++nf2) {
                const uint32_t off =
                    SW128((uint32_t)((n0w + nf2 * 16 + b_lr) * 128 + kf * 32 + b_lc));
                ldsm_x4(bh[nf2], bhb + off);
                ldsm_x4(bl[nf2], blb + off);
            }
#pragma unroll
            for (int mf = 0; mf < 2; ++mf)
#pragma unroll
                for (int nf = 0; nf < 4; ++nf) {
                    const uint32_t* bhp = &bh[nf >> 1][(nf & 1) * 2];
                    const uint32_t* blp = &bl[nf >> 1][(nf & 1) * 2];
                    mma_bf16(acc[mf][nf], ah[mf], bhp);
                    mma_bf16(acc[mf][nf], ah[mf], blp);
                    mma_bf16(acc[mf][nf], al[mf], bhp);
                }
        }

        if (c < 3) {
            __syncthreads();
            stA(dsm, ((c + 1) & 1) * 65536, tid, fa);
            cp_wait<0>();
        }
        __syncthreads();
    }

#pragma unroll
    for (int mf = 0; mf < 2; ++mf) {
        const int rg = row0 + m0w + mf * 16 + (lane >> 2);
#pragma unroll
        for (int nf = 0; nf < 4; ++nf) {
            const int cg = n0g + n0w + nf * 8 + ((lane & 3) << 1);
            *(float2*)&g_xproj[(size_t)rg * GG + cg] =
                make_float2(acc[mf][nf][0], acc[mf][nf][1]);
            *(float2*)&g_xproj[(size_t)(rg + 8) * GG + cg] =
                make_float2(acc[mf][nf][2], acc[mf][nf][3]);
        }
    }
}

// f-tile: fg for (batch b, t in [chunk*128, +128)). sig tile via smem; fk
// column + bias held in caller registers (u = tid & 127 is CTA-constant).
__device__ void f_tile(char* dsm, const float* __restrict__ sig,
                       const float* wk, float bf, int b, int chunk, int tid) {
    float* ss = (float*)(dsm + FK_OFF);
    const size_t bt0 = (size_t)b * TT + chunk * 128;
    for (int i = tid; i < 128 * 20; i += 512)
        ss[i] = sig[bt0 * 20 + i];
    __syncthreads();
    const int u  = tid & 127;
    const int th = tid >> 7;   // 0..3 -> 32 t each
#pragma unroll 4
    for (int i = 0; i < 32; ++i) {
        const int t = th * 32 + i;
        float s = bf;
        const float* sr = ss + t * 20;
#pragma unroll
        for (int k = 0; k < 20; ++k) s = fmaf(sr[k], wk[k], s);
        g_fg[(bt0 + t) * UU + u] = fsig(s);
    }
}

// ---------------------------------------------------------------------------
// Scan body: 512 threads (16 warps). Warp w owns u-slice [8w, 8w+8) in all 3
// gate regions: col(nc) = nc*128 + 8w + (lane>>2). Thread handles batch
// brow = lane>>2, u = 8w + 2(lane&3): full cell update in registers, 8 MUFU.
// A-fragment write: STS.64 {hi(u,u+1), lo(u,u+1)} at
//   As[brow*AS_ROW + (w>>1)*16 + (lane&3)*4 + (w&1)*2]   (m16n8k16 A layout).
// ---------------------------------------------------------------------------
#define XS_ROW 388
#define XS_F   (8 * XS_ROW)  // 3104
#define FS_ROW 132
#define FS_F   (8 * FS_ROW)  // 1056
#define AS_ROW 144
#define AS_W   (8 * AS_ROW)  // 1152 u32 per buffer
#define XS_OFF 0
#define FS_OFF (2 * XS_F)
#define AS_OFF (2 * XS_F + 2 * FS_F)

__device__ __forceinline__ void wait_chunk(int c, int b0g, int tid) {
    if (tid < 8) {
        volatile int* f = (volatile int*)&g_flags[c * 256 + b0g + tid];
        while (*f < 4) {}
        __threadfence();
    }
}

__device__ void scan_body(char* dsm, const float* __restrict__ bias,
                          float* __restrict__ out, int bid, int tid) {
    float* sm = (float*)dsm;
    float* xs = sm + XS_OFF;
    float* fs = sm + FS_OFF;
    uint32_t* As = (uint32_t*)(sm + AS_OFF);
    const uint32_t smu = s2u(sm);

    const int wid  = tid >> 5;
    const int lane = tid & 31;
    const int b0g  = bid * 8;

    for (int i = tid; i < 2 * AS_W; i += 512) As[i] = 0;

    // rk B-fragments: col n = nc*128 + 8*wid + (lane>>2)
    uint32_t wfr[8][3][2];
#pragma unroll
    for (int kc = 0; kc < 8; ++kc)
#pragma unroll
        for (int nc = 0; nc < 3; ++nc) {
            const int n = nc * 128 + 8 * wid + (lane >> 2);
            const int k = kc * 16 + (lane & 3) * 2;
            wfr[kc][nc][0] = *(const uint32_t*)&g_rk[(size_t)n * UU + k];
            wfr[kc][nc][1] = *(const uint32_t*)&g_rk[(size_t)n * UU + k + 8];
        }

    float bb0[3], bb1[3], pp[3];
#pragma unroll
    for (int nc = 0; nc < 3; ++nc) {
        const int c = nc * 128 + 8 * wid + (lane & 3) * 2;
        bb0[nc] = (c < UU) ? bias[c] : bias[c + UU];
        bb1[nc] = (c + 1 < UU) ? bias[c + 1] : bias[c + 1 + UU];
        pp[nc]  = (nc == 1) ? 1.0f : 0.5f;
    }

    float cst[2] = {0.f, 0.f};

#define PREFETCH(t)                                                            \
    {                                                                          \
        const int _buf = (t) & 1;                                              \
        {                                                                      \
            const int r = tid / 96, o = tid % 96;                              \
            cp16(smu + (XS_OFF + _buf * XS_F + r * XS_ROW + o * 4) * 4,        \
                 &g_xproj[((size_t)(b0g + r) * TT + (t)) * GG + o * 4]);       \
        }                                                                      \
        {                                                                      \
            const int id = tid + 512;                                          \
            if (id < 768) {                                                    \
                const int r = id / 96, o = id % 96;                            \
                cp16(smu + (XS_OFF + _buf * XS_F + r * XS_ROW + o * 4) * 4,    \
                     &g_xproj[((size_t)(b0g + r) * TT + (t)) * GG + o * 4]);   \
            }                                                                  \
        }                                                                      \
        if (tid < 256) {                                                       \
            cp16(smu + (FS_OFF + _buf * FS_F + (tid >> 5) * FS_ROW +           \
                        (tid & 31) * 4) * 4,                                   \
                 &g_fg[((size_t)(b0g + (tid >> 5)) * TT + (t)) * UU +          \
                       (tid & 31) * 4]);                                       \
        }                                                                      \
        cp_commit();                                                           \
    }

    wait_chunk(0, b0g, tid);
    __syncthreads();
    PREFETCH(0);

    const int brow = lane >> 2;
    const int q4   = (lane & 3) * 4;
    const int ucol = 8 * wid + (lane & 3) * 2;
    const int wsl  = (wid >> 1) * 16 + q4 + (wid & 1) * 2;   // STS.64 slot

    for (int t = 0; t < TT; ++t) {
        cp_wait<0>();
        __syncthreads();

        const uint32_t* Ar = As + (t & 1) * AS_W;
        uint32_t* Aw = As + ((t + 1) & 1) * AS_W;

        const float* xb = xs + (t & 1) * XS_F + brow * XS_ROW;
        float acc[3][4];
#pragma unroll
        for (int nc = 0; nc < 3; ++nc) {
            const float2 xv = *(const float2*)&xb[nc * 128 + ucol];
            acc[nc][0] = xv.x; acc[nc][1] = xv.y;
            acc[nc][2] = 0.f;  acc[nc][3] = 0.f;
        }

        if (t + 1 < TT) {
            if (((t + 1) & 127) == 0) {
                wait_chunk((t + 1) >> 7, b0g, tid);
                __syncthreads();
            }
            PREFETCH(t + 1);
        }

#pragma unroll
        for (int kc = 0; kc < 8; ++kc) {
            const uint4 av = *(const uint4*)&Ar[brow * AS_ROW + kc * 16 + q4];
            uint32_t af[4] = {av.x, av.y, av.z, av.w};
#pragma unroll
            for (int nc = 0; nc < 3; ++nc)
                mma_bf16(acc[nc], af, wfr[kc][nc]);
        }

        float gv[3][2];
#pragma unroll
        for (int nc = 0; nc < 3; ++nc) {
            const float p = pp[nc], q = 1.0f - p;
            const float g0 = acc[nc][0] + acc[nc][2] + bb0[nc];
            const float g1 = acc[nc][1] + acc[nc][3] + bb1[nc];
            gv[nc][0] = fmaf(tanh_apx(g0 * p), p, q);
            gv[nc][1] = fmaf(tanh_apx(g1 * p), p, q);
        }

        const float2 fv =
            *(const float2*)&fs[(t & 1) * FS_F + brow * FS_ROW + ucol];
        cst[0] = fmaf(fv.x, cst[0], gv[0][0] * gv[1][0]);
        cst[1] = fmaf(fv.y, cst[1], gv[0][1] * gv[1][1]);
        const float h0 = gv[2][0] * tanh_apx(cst[0]);
        const float h1 = gv[2][1] * tanh_apx(cst[1]);

        *(float2*)&out[((size_t)(b0g + brow) * TT + t) * UU + ucol] =
            make_float2(h0, h1);

        uint2 hv;
        hv.x = pack_hi2(h0, h1);
        hv.y = pack_lo2(h0, h1);
        *(uint2*)&Aw[brow * AS_ROW + wsl] = hv;
    }
}

// ---------------------------------------------------------------------------
// Megakernel: one wave of 148 CTAs (141KB smem => 1 CTA/SM).
// bids [0,32): scan. bids [32,148): workers over 8192 jobs, chunk-major:
// job = (chunk, batch, kind); kind 0..2 = gemm N-tiles, kind 3 = fgate tile.
// ---------------------------------------------------------------------------
__global__ __launch_bounds__(512, 1)
void mega_kernel(const float* __restrict__ inputs,
                 const float* __restrict__ signatures,
                 const float* __restrict__ fkern,
                 const float* __restrict__ bias,
                 float* __restrict__ out) {
    extern __shared__ __align__(16) char dsm[];
    const int bid = blockIdx.x;
    const int tid = threadIdx.x;

    if (bid < NSCAN) {
        scan_body(dsm, bias, out, bid, tid);
    } else {
        float wk[20];
        const int uf = tid & 127;
#pragma unroll
        for (int k = 0; k < 20; ++k) wk[k] = __ldg(&fkern[k * UU + uf]);
        const float bf = __ldg(&bias[UU + uf]);

        for (int tau = bid - NSCAN; tau < NJOB; tau += NWORK) {
            const int chunk = tau >> 10;
            const int j     = tau & 1023;
            const int b     = j >> 2;
            const int kind  = j & 3;
            if (kind < 3) {
                gemm_tile(dsm, inputs, kind * 128, b * 1024 + chunk * 128, tid);
            } else {
                f_tile(dsm, signatures, wk, bf, b, chunk, tid);
            }
            __syncthreads();
            if (tid == 0) {
                __threadfence();
                atomicAdd(&g_flags[chunk * 256 + b], 1);
            }
        }
    }
}

// ---------------------------------------------------------------------------
extern "C" void kernel_launch(void* const* d_in, const int* in_sizes, int n_in,
                              void* d_out, int out_size) {
    const float* inputs     = (const float*)d_in[0];
    const float* signatures = (const float*)d_in[1];
    const float* ikern      = (const float*)d_in[2];
    const float* rkern      = (const float*)d_in[3];
    const float* fkern      = (const float*)d_in[4];
    const float* bias       = (const float*)d_in[5];
    float* out = (float*)d_out;

    (void)in_sizes; (void)n_in; (void)out_size;

    static bool init = false;
    if (!init) {
        cudaFuncSetAttribute(mega_kernel,
                             cudaFuncAttributeMaxDynamicSharedMemorySize,
                             MEGA_SMEM);
        init = true;
    }

    zero_flags<<<8, 256>>>();
    convert_b<<<GG, DD>>>(ikern);
    convert_rk<<<GG, UU>>>(rkern);
    mega_kernel<<<NBLK, 512, MEGA_SMEM>>>(inputs, signatures, fkern, bias, out);
}